// round 15
// baseline (speedup 1.0000x reference)
#include <cuda_runtime.h>
#include <cuda_bf16.h>
#include <cuda_fp16.h>
#include <cstdint>

// ============================================================================
// KLinear: y[i,n] = (sum_k kron(a_k,b_k)[i,j] / (2*sqrt(8))) * x[n,j] + bias[n]
//
// fp16 single-product GEMM (calibrated rel_err 2.93e-4), fp32 accum.
// Round-15: 3 CTAs/SM (3 warps/SMSP, 3 independent barrier domains) to cut
// tensor-pipe co-stall (R14: tensor=73%, 2 warps/SMSP).
//   * CTA 128x128, 4 warps (2Mx2N), warp tile 64x64
//   * 2-stage x 32KB pipeline -> 64KB smem/CTA -> 3 CTAs/SM (192KB)
//   * __launch_bounds__(128,3): reg cap 170; nb-loop split keeps live set
//     ~= 128 accum + 16 fA + 8 fB
//   * K-split 3 (22/21/21 ktiles) -> 3072 CTAs = 6.92 waves @ 444 concurrent
//   * out prefilled with bias (fused into split_x); epilogue red.global.add
// ============================================================================

#define N_DIM 4096

// ---------------- scratch (device globals; no runtime allocation) ----------
__device__ __half g_Wh[(size_t)N_DIM * N_DIM];
__device__ __half g_Xh[(size_t)N_DIM * N_DIM];

// ---------------- helpers ---------------------------------------------------
#define SMEM_SWIZZLE_128B(o) ((o) ^ (((o) >> 3) & 0x70))

__device__ __forceinline__ uint32_t smem_u32(const void* p) {
    uint32_t a;
    asm("{ .reg .u64 t; cvta.to.shared.u64 t, %1; cvt.u32.u64 %0, t; }"
        : "=r"(a) : "l"(p));
    return a;
}

__device__ __forceinline__ void cp_async16(uint32_t dst, const void* src) {
    asm volatile("cp.async.cg.shared.global [%0], [%1], 16;"
                 :: "r"(dst), "l"(src) : "memory");
}

__device__ __forceinline__ void ldm_x4(uint32_t (&r)[4], uint32_t addr) {
    asm volatile("ldmatrix.sync.aligned.m8n8.x4.shared.b16 {%0,%1,%2,%3}, [%4];"
                 : "=r"(r[0]), "=r"(r[1]), "=r"(r[2]), "=r"(r[3])
                 : "r"(addr));
}

__device__ __forceinline__ void mma_fp16(float (&d)[4], const uint32_t (&a)[4],
                                         uint32_t b0, uint32_t b1) {
    asm volatile(
        "mma.sync.aligned.m16n8k16.row.col.f32.f16.f16.f32 "
        "{%0,%1,%2,%3}, {%4,%5,%6,%7}, {%8,%9}, {%0,%1,%2,%3};"
        : "+f"(d[0]), "+f"(d[1]), "+f"(d[2]), "+f"(d[3])
        : "r"(a[0]), "r"(a[1]), "r"(a[2]), "r"(a[3]), "r"(b0), "r"(b1));
}

__device__ __forceinline__ void red_add_v2(float* ptr, float v0, float v1) {
    asm volatile("red.global.add.v2.f32 [%0], {%1, %2};"
                 :: "l"(ptr), "f"(v0), "f"(v1) : "memory");
}

// ---------------- kernel 1: build W in fp32, store fp16 (8 elems/thread) ---
__global__ __launch_bounds__(256) void build_w_kernel(
    const float* __restrict__ a0, const float* __restrict__ a1,
    const float* __restrict__ a2, const float* __restrict__ a3,
    const float* __restrict__ a4, const float* __restrict__ a5,
    const float* __restrict__ a6, const float* __restrict__ a7,
    const float* __restrict__ b0, const float* __restrict__ b1,
    const float* __restrict__ b2, const float* __restrict__ b3,
    const float* __restrict__ b4, const float* __restrict__ b5,
    const float* __restrict__ b6, const float* __restrict__ b7)
{
    const int t = blockIdx.x * blockDim.x + threadIdx.x;  // 0 .. 2.097M-1
    const int i  = t >> 9;          // row 0..4095
    const int j0 = (t & 511) << 3;  // 8-aligned col

    const float av0 = a0[(i >> 6) * 64  + (j0 >> 6)];
    const float av1 = a1[(i >> 6) * 64  + (j0 >> 6)];
    const float av2 = a2[(i >> 7) * 32  + (j0 >> 7)];
    const float av3 = a3[(i >> 5) * 128 + (j0 >> 5)];
    const float av4 = a4[(i >> 8) * 16  + (j0 >> 8)];
    const float av5 = a5[(i >> 4) * 256 + (j0 >> 4)];
    const float av6 = a6[(i >> 9) * 8   + (j0 >> 9)];
    const float av7 = a7[(i >> 3) * 512 + (j0 >> 3)];

    const float4* p0 = reinterpret_cast<const float4*>(b0 + (i & 63)  * 64  + (j0 & 63));
    const float4* p1 = reinterpret_cast<const float4*>(b1 + (i & 63)  * 64  + (j0 & 63));
    const float4* p2 = reinterpret_cast<const float4*>(b2 + (i & 127) * 128 + (j0 & 127));
    const float4* p3 = reinterpret_cast<const float4*>(b3 + (i & 31)  * 32  + (j0 & 31));
    const float4* p4 = reinterpret_cast<const float4*>(b4 + (i & 255) * 256 + (j0 & 255));
    const float4* p5 = reinterpret_cast<const float4*>(b5 + (i & 15)  * 16  + (j0 & 15));
    const float4* p6 = reinterpret_cast<const float4*>(b6 + (i & 511) * 512 + (j0 & 511));
    const float4* p7 = reinterpret_cast<const float4*>(b7 + (i & 7)   * 8   + (j0 & 7));

    float s[8];
#pragma unroll
    for (int e = 0; e < 8; ++e) s[e] = 0.0f;

#pragma unroll
    for (int h = 0; h < 2; ++h) {
        float4 v0 = p0[h], v1 = p1[h], v2 = p2[h], v3 = p3[h];
        float4 v4 = p4[h], v5 = p5[h], v6 = p6[h], v7 = p7[h];
        float* e0 = &v0.x; float* e1 = &v1.x; float* e2 = &v2.x; float* e3 = &v3.x;
        float* e4 = &v4.x; float* e5 = &v5.x; float* e6 = &v6.x; float* e7 = &v7.x;
#pragma unroll
        for (int e = 0; e < 4; ++e) {
            float acc = av0 * e0[e];
            acc = fmaf(av1, e1[e], acc);
            acc = fmaf(av2, e2[e], acc);
            acc = fmaf(av3, e3[e], acc);
            acc = fmaf(av4, e4[e], acc);
            acc = fmaf(av5, e5[e], acc);
            acc = fmaf(av6, e6[e], acc);
            acc = fmaf(av7, e7[e], acc);
            s[h * 4 + e] = acc * 0.17677669529663687f;  // 1/(2*sqrt(8))
        }
    }

    __half h8[8];
#pragma unroll
    for (int e = 0; e < 8; ++e) h8[e] = __float2half_rn(s[e]);
    *reinterpret_cast<uint4*>(g_Wh + (size_t)i * N_DIM + j0) =
        *reinterpret_cast<uint4*>(h8);
}

// ---------------- kernel 2: X -> fp16, and out := broadcast(bias) ----------
__global__ __launch_bounds__(256) void split_x_init_kernel(
    const float* __restrict__ x, const float* __restrict__ bias,
    float* __restrict__ out)
{
    const int i = blockIdx.x * blockDim.x + threadIdx.x;  // float4 index
    float4 v = reinterpret_cast<const float4*>(x)[i];
    __half2 h0 = __floats2half2_rn(v.x, v.y);
    __half2 h1 = __floats2half2_rn(v.z, v.w);
    reinterpret_cast<__half2*>(g_Xh)[2 * i]     = h0;
    reinterpret_cast<__half2*>(g_Xh)[2 * i + 1] = h1;

    // out init: same float4 geometry (4096x4096 f32), col/4 = i & 1023
    reinterpret_cast<float4*>(out)[i] =
        reinterpret_cast<const float4*>(bias)[i & 1023];
}

// ---------------- kernel 3: fp16 mma.sync GEMM ------------------------------
// CTA tile 128(M) x 128(N), 128 threads (4 warps, 2Mx2N, warp tile 64x64).
// K-split 3: 22/21/21 ktiles of 64. SMEM: 2 stages x 32KB:
//   +0      W (128 x 64 fp16, SW128-swizzled 128B rows)  = 16KB
//   +16384  X (128 x 64 fp16)                            = 16KB
static constexpr int SM_BUFSZ   = 32768;
static constexpr int NSTAGE     = 2;
static constexpr int SMEM_TOTAL = NSTAGE * SM_BUFSZ;  // 65536

__global__ __launch_bounds__(128, 3)
void gemm_kernel(float* __restrict__ out)
{
    extern __shared__ __align__(1024) char smem[];
    const uint32_t sb = smem_u32(smem);
    const int tid = threadIdx.x;
    const int wid = tid >> 5;
    const int lid = tid & 31;

    const int rbase = blockIdx.x * 128;        // M rows (W / OUTF)
    const int nbase = blockIdx.y * 128;        // N rows (X / BATCH)
    // K-split 3: z=0 -> ktiles [0,22), z=1 -> [22,43), z=2 -> [43,64)
    const int z = blockIdx.z;
    const int t0 = (z == 0) ? 0 : (22 + 21 * (z - 1));
    const int nkt = (z == 0) ? 22 : 21;

    const int warp_m = wid & 1;   // 0..1 -> 64-row slab
    const int warp_n = wid >> 1;  // 0..1 -> 64-col slab

    const int lj   = lid & 7;   // row-within-8 for ldmatrix
    const int lsel = lid >> 3;  // which 8x8 matrix this lane feeds

    // ---- cp.async stage loader: 2048 chunks of 16B, 16 per thread ---------
    auto load_stage = [&](int t) {
        if (t < nkt) {
            const uint32_t bufb = sb + (uint32_t)(t & 1) * SM_BUFSZ;
            const int k0 = (t0 + t) * 64;
#pragma unroll
            for (int s = 0; s < 8; ++s) {        // W: 1024 chunks (128 rows)
                const int c   = tid + s * 128;
                const int row = c >> 3;
                const int ch  = c & 7;
                const uint32_t sw =
                    SMEM_SWIZZLE_128B((uint32_t)(row * 128 + ch * 16));
                cp_async16(bufb + sw,
                           g_Wh + (size_t)(rbase + row) * N_DIM + k0 + ch * 8);
            }
#pragma unroll
            for (int s = 0; s < 8; ++s) {        // X: 1024 chunks (128 rows)
                const int c   = tid + s * 128;
                const int row = c >> 3;
                const int ch  = c & 7;
                const uint32_t sw =
                    SMEM_SWIZZLE_128B((uint32_t)(row * 128 + ch * 16));
                cp_async16(bufb + 16384 + sw,
                           g_Xh + (size_t)(nbase + row) * N_DIM + k0 + ch * 8);
            }
        }
        asm volatile("cp.async.commit_group;" ::: "memory");
    };

    // ---- accumulators: 4 m16-blocks x 8 n8-blocks x 4 regs = 128 ----------
    float d[4][8][4];
#pragma unroll
    for (int mb = 0; mb < 4; ++mb)
#pragma unroll
        for (int q = 0; q < 8; ++q)
#pragma unroll
            for (int r = 0; r < 4; ++r) d[mb][q][r] = 0.0f;

    load_stage(0);

    for (int t = 0; t < nkt; ++t) {
        load_stage(t + 1);
        // stage t resident (newest group still pending)
        asm volatile("cp.async.wait_group 1;" ::: "memory");
        __syncthreads();

        const uint32_t bufb = sb + (uint32_t)(t & 1) * SM_BUFSZ;

#pragma unroll
        for (int ks = 0; ks < 4; ++ks) {
            const int kc = ks * 2;  // 16B-chunk index of this k16 step

            // A fragments (rows = M): 4 x m16 (64-row warp slab)
            uint32_t fA[4][4];
#pragma unroll
            for (int mb = 0; mb < 4; ++mb) {
                const int row = warp_m * 64 + mb * 16 + lj + ((lsel & 1) << 3);
                const int ch  = kc + (lsel >> 1);
                ldm_x4(fA[mb], bufb +
                       SMEM_SWIZZLE_128B((uint32_t)(row * 128 + ch * 16)));
            }

            // B fragments in 2 halves to bound live registers (~8 regs)
#pragma unroll
            for (int half = 0; half < 2; ++half) {
                uint32_t fB[2][4];
#pragma unroll
                for (int nb = 0; nb < 2; ++nb) {
                    const int nbg = half * 2 + nb;
                    const int row = warp_n * 64 + nbg * 16 + lj +
                                    ((lsel >> 1) << 3);
                    const int ch  = kc + (lsel & 1);
                    ldm_x4(fB[nb], bufb + 16384 +
                           SMEM_SWIZZLE_128B((uint32_t)(row * 128 + ch * 16)));
                }
#pragma unroll
                for (int mb = 0; mb < 4; ++mb) {
#pragma unroll
                    for (int nb = 0; nb < 2; ++nb) {
                        const int q = (half * 2 + nb) * 2;
                        mma_fp16(d[mb][q + 0], fA[mb], fB[nb][0], fB[nb][1]);
                        mma_fp16(d[mb][q + 1], fA[mb], fB[nb][2], fB[nb][3]);
                    }
                }
            }
        }
        __syncthreads();
    }

    asm volatile("cp.async.wait_group 0;" ::: "memory");

    // ---- epilogue: regs -> gmem via f32 reduction (bias pre-filled) -------
    // d-frag: d0,d1 -> row (lid>>2),   cols (lid&3)*2 + {0,1}
    //         d2,d3 -> row (lid>>2)+8, same cols
    const int rw = rbase + warp_m * 64 + (lid >> 2);
    const int cw = nbase + warp_n * 64 + (lid & 3) * 2;
#pragma unroll
    for (int mb = 0; mb < 4; ++mb) {
#pragma unroll
        for (int q = 0; q < 8; ++q) {
            const int col = cw + q * 8;
            const int r0  = rw + mb * 16;
            red_add_v2(out + (size_t)r0 * N_DIM + col,
                       d[mb][q][0], d[mb][q][1]);
            red_add_v2(out + (size_t)(r0 + 8) * N_DIM + col,
                       d[mb][q][2], d[mb][q][3]);
        }
    }
}

// ---------------- launch ----------------------------------------------------
extern "C" void kernel_launch(void* const* d_in, const int* in_sizes, int n_in,
                              void* d_out, int out_size)
{
    const float* x    = (const float*)d_in[0];
    const float* a[8] = {(const float*)d_in[1], (const float*)d_in[2],
                         (const float*)d_in[3], (const float*)d_in[4],
                         (const float*)d_in[5], (const float*)d_in[6],
                         (const float*)d_in[7], (const float*)d_in[8]};
    const float* b[8] = {(const float*)d_in[9],  (const float*)d_in[10],
                         (const float*)d_in[11], (const float*)d_in[12],
                         (const float*)d_in[13], (const float*)d_in[14],
                         (const float*)d_in[15], (const float*)d_in[16]};
    const float* bias = (const float*)d_in[17];
    float* out = (float*)d_out;

    cudaFuncSetAttribute(gemm_kernel,
                         cudaFuncAttributeMaxDynamicSharedMemorySize,
                         SMEM_TOTAL);

    // 1) W build (fp32 math, fp16 store): 8 outputs/thread
    build_w_kernel<<<(N_DIM * N_DIM / 8) / 256, 256>>>(
        a[0], a[1], a[2], a[3], a[4], a[5], a[6], a[7],
        b[0], b[1], b[2], b[3], b[4], b[5], b[6], b[7]);

    // 2) X -> fp16, fused with out := broadcast(bias)
    split_x_init_kernel<<<(N_DIM * N_DIM / 4) / 256, 256>>>(x, bias, out);

    // 3) GEMM: 32x32x3 grid (128x128 tiles, K split 22/21/21), 128 threads
    gemm_kernel<<<dim3(32, 32, 3), 128, SMEM_TOTAL>>>(out);
}

// round 16
// speedup vs baseline: 1.2710x; 1.2710x over previous
#include <cuda_runtime.h>
#include <cuda_bf16.h>
#include <cuda_fp16.h>
#include <cstdint>

// ============================================================================
// KLinear: y[i,n] = (sum_k kron(a_k,b_k)[i,j] / (2*sqrt(8))) * x[n,j] + bias[n]
//
// fp16 single-product GEMM (calibrated rel_err 2.93e-4), fp32 accum.
// Round-16: GEMM = R14 verbatim (best: 308us, tensor 73.2%). Non-GEMM
// overhead attacked: build_w + split_x + bias-init fused into ONE prep
// kernel (latency-bound W-build overlaps DRAM-bound X-convert/out-init).
// R15 lesson: occupancy-3 unreachable (reg cap 170 spills 128-accum body);
// 2-stage pipeline under-covers cp.async latency. Reverted.
// ============================================================================

#define N_DIM 4096

// ---------------- scratch (device globals; no runtime allocation) ----------
__device__ __half g_Wh[(size_t)N_DIM * N_DIM];
__device__ __half g_Xh[(size_t)N_DIM * N_DIM];

// ---------------- helpers ---------------------------------------------------
#define SMEM_SWIZZLE_128B(o) ((o) ^ (((o) >> 3) & 0x70))

__device__ __forceinline__ uint32_t smem_u32(const void* p) {
    uint32_t a;
    asm("{ .reg .u64 t; cvta.to.shared.u64 t, %1; cvt.u32.u64 %0, t; }"
        : "=r"(a) : "l"(p));
    return a;
}

__device__ __forceinline__ void cp_async16(uint32_t dst, const void* src) {
    asm volatile("cp.async.cg.shared.global [%0], [%1], 16;"
                 :: "r"(dst), "l"(src) : "memory");
}

__device__ __forceinline__ void ldm_x4(uint32_t (&r)[4], uint32_t addr) {
    asm volatile("ldmatrix.sync.aligned.m8n8.x4.shared.b16 {%0,%1,%2,%3}, [%4];"
                 : "=r"(r[0]), "=r"(r[1]), "=r"(r[2]), "=r"(r[3])
                 : "r"(addr));
}

__device__ __forceinline__ void mma_fp16(float (&d)[4], const uint32_t (&a)[4],
                                         uint32_t b0, uint32_t b1) {
    asm volatile(
        "mma.sync.aligned.m16n8k16.row.col.f32.f16.f16.f32 "
        "{%0,%1,%2,%3}, {%4,%5,%6,%7}, {%8,%9}, {%0,%1,%2,%3};"
        : "+f"(d[0]), "+f"(d[1]), "+f"(d[2]), "+f"(d[3])
        : "r"(a[0]), "r"(a[1]), "r"(a[2]), "r"(a[3]), "r"(b0), "r"(b1));
}

__device__ __forceinline__ void red_add_v2(float* ptr, float v0, float v1) {
    asm volatile("red.global.add.v2.f32 [%0], {%1, %2};"
                 :: "l"(ptr), "f"(v0), "f"(v1) : "memory");
}

// ---------------- kernel 1: fused prep ---------------------------------------
// blocks [0, 8192):      build W (fp32 math) -> fp16, 8 elems/thread
// blocks [8192, 24576):  X -> fp16  AND  out := broadcast(bias)
__global__ __launch_bounds__(256) void prep_kernel(
    const float* __restrict__ x, const float* __restrict__ bias,
    float* __restrict__ out,
    const float* __restrict__ a0, const float* __restrict__ a1,
    const float* __restrict__ a2, const float* __restrict__ a3,
    const float* __restrict__ a4, const float* __restrict__ a5,
    const float* __restrict__ a6, const float* __restrict__ a7,
    const float* __restrict__ b0, const float* __restrict__ b1,
    const float* __restrict__ b2, const float* __restrict__ b3,
    const float* __restrict__ b4, const float* __restrict__ b5,
    const float* __restrict__ b6, const float* __restrict__ b7)
{
    if (blockIdx.x < 8192) {
        // ---- W build: 2.097M threads x 8 outputs ----
        const int t = blockIdx.x * 256 + threadIdx.x;
        const int i  = t >> 9;          // row 0..4095
        const int j0 = (t & 511) << 3;  // 8-aligned col

        const float av0 = a0[(i >> 6) * 64  + (j0 >> 6)];
        const float av1 = a1[(i >> 6) * 64  + (j0 >> 6)];
        const float av2 = a2[(i >> 7) * 32  + (j0 >> 7)];
        const float av3 = a3[(i >> 5) * 128 + (j0 >> 5)];
        const float av4 = a4[(i >> 8) * 16  + (j0 >> 8)];
        const float av5 = a5[(i >> 4) * 256 + (j0 >> 4)];
        const float av6 = a6[(i >> 9) * 8   + (j0 >> 9)];
        const float av7 = a7[(i >> 3) * 512 + (j0 >> 3)];

        const float4* p0 = reinterpret_cast<const float4*>(b0 + (i & 63)  * 64  + (j0 & 63));
        const float4* p1 = reinterpret_cast<const float4*>(b1 + (i & 63)  * 64  + (j0 & 63));
        const float4* p2 = reinterpret_cast<const float4*>(b2 + (i & 127) * 128 + (j0 & 127));
        const float4* p3 = reinterpret_cast<const float4*>(b3 + (i & 31)  * 32  + (j0 & 31));
        const float4* p4 = reinterpret_cast<const float4*>(b4 + (i & 255) * 256 + (j0 & 255));
        const float4* p5 = reinterpret_cast<const float4*>(b5 + (i & 15)  * 16  + (j0 & 15));
        const float4* p6 = reinterpret_cast<const float4*>(b6 + (i & 511) * 512 + (j0 & 511));
        const float4* p7 = reinterpret_cast<const float4*>(b7 + (i & 7)   * 8   + (j0 & 7));

        float s[8];
#pragma unroll
        for (int e = 0; e < 8; ++e) s[e] = 0.0f;

#pragma unroll
        for (int h = 0; h < 2; ++h) {
            float4 v0 = p0[h], v1 = p1[h], v2 = p2[h], v3 = p3[h];
            float4 v4 = p4[h], v5 = p5[h], v6 = p6[h], v7 = p7[h];
            float* e0 = &v0.x; float* e1 = &v1.x; float* e2 = &v2.x; float* e3 = &v3.x;
            float* e4 = &v4.x; float* e5 = &v5.x; float* e6 = &v6.x; float* e7 = &v7.x;
#pragma unroll
            for (int e = 0; e < 4; ++e) {
                float acc = av0 * e0[e];
                acc = fmaf(av1, e1[e], acc);
                acc = fmaf(av2, e2[e], acc);
                acc = fmaf(av3, e3[e], acc);
                acc = fmaf(av4, e4[e], acc);
                acc = fmaf(av5, e5[e], acc);
                acc = fmaf(av6, e6[e], acc);
                acc = fmaf(av7, e7[e], acc);
                s[h * 4 + e] = acc * 0.17677669529663687f;  // 1/(2*sqrt(8))
            }
        }

        __half h8[8];
#pragma unroll
        for (int e = 0; e < 8; ++e) h8[e] = __float2half_rn(s[e]);
        *reinterpret_cast<uint4*>(g_Wh + (size_t)i * N_DIM + j0) =
            *reinterpret_cast<uint4*>(h8);
    } else {
        // ---- X convert + out init: 4.19M float4 threads ----
        const int i = (blockIdx.x - 8192) * 256 + threadIdx.x;
        float4 v = reinterpret_cast<const float4*>(x)[i];
        __half2 h0 = __floats2half2_rn(v.x, v.y);
        __half2 h1 = __floats2half2_rn(v.z, v.w);
        reinterpret_cast<__half2*>(g_Xh)[2 * i]     = h0;
        reinterpret_cast<__half2*>(g_Xh)[2 * i + 1] = h1;

        reinterpret_cast<float4*>(out)[i] =
            reinterpret_cast<const float4*>(bias)[i & 1023];
    }
}

// ---------------- kernel 2: fp16 mma.sync GEMM (R14 verbatim) ---------------
// CTA tile 128(M) x 128(N), K-half = 2048 (32 ktiles of 64), 128 threads
// (4 warps, 2Mx2N, warp tile 64x64). SMEM: 3 stages x 32KB:
//   +0      W (128 x 64 fp16, SW128-swizzled 128B rows)  = 16KB
//   +16384  X (128 x 64 fp16)                            = 16KB
static constexpr int SM_BUFSZ   = 32768;
static constexpr int NSTAGE     = 3;
static constexpr int SMEM_TOTAL = NSTAGE * SM_BUFSZ;  // 98304
static constexpr int KTILES     = 32;                 // per K-half

__global__ __launch_bounds__(128, 2)
void gemm_kernel(float* __restrict__ out)
{
    extern __shared__ __align__(1024) char smem[];
    const uint32_t sb = smem_u32(smem);
    const int tid = threadIdx.x;
    const int wid = tid >> 5;
    const int lid = tid & 31;

    const int rbase = blockIdx.x * 128;        // M rows (W / OUTF)
    const int nbase = blockIdx.y * 128;        // N rows (X / BATCH)
    const int kbase = blockIdx.z * 2048;       // K half

    const int warp_m = wid & 1;   // 0..1 -> 64-row slab
    const int warp_n = wid >> 1;  // 0..1 -> 64-col slab

    const int lj   = lid & 7;   // row-within-8 for ldmatrix
    const int lsel = lid >> 3;  // which 8x8 matrix this lane feeds

    // ---- cp.async stage loader: 2048 chunks of 16B, 16 per thread ---------
    auto load_stage = [&](int t) {
        if (t < KTILES) {
            const uint32_t bufb =
                sb + (uint32_t)(t % NSTAGE) * SM_BUFSZ;
            const int k0 = kbase + t * 64;
#pragma unroll
            for (int s = 0; s < 8; ++s) {        // W: 1024 chunks (128 rows)
                const int c   = tid + s * 128;
                const int row = c >> 3;
                const int ch  = c & 7;
                const uint32_t sw =
                    SMEM_SWIZZLE_128B((uint32_t)(row * 128 + ch * 16));
                cp_async16(bufb + sw,
                           g_Wh + (size_t)(rbase + row) * N_DIM + k0 + ch * 8);
            }
#pragma unroll
            for (int s = 0; s < 8; ++s) {        // X: 1024 chunks (128 rows)
                const int c   = tid + s * 128;
                const int row = c >> 3;
                const int ch  = c & 7;
                const uint32_t sw =
                    SMEM_SWIZZLE_128B((uint32_t)(row * 128 + ch * 16));
                cp_async16(bufb + 16384 + sw,
                           g_Xh + (size_t)(nbase + row) * N_DIM + k0 + ch * 8);
            }
        }
        asm volatile("cp.async.commit_group;" ::: "memory");
    };

    // ---- accumulators: 4 m16-blocks x 8 n8-blocks x 4 regs = 128 ----------
    float d[4][8][4];
#pragma unroll
    for (int mb = 0; mb < 4; ++mb)
#pragma unroll
        for (int q = 0; q < 8; ++q)
#pragma unroll
            for (int r = 0; r < 4; ++r) d[mb][q][r] = 0.0f;

    load_stage(0);
    load_stage(1);

    for (int t = 0; t < KTILES; ++t) {
        // stage t resident (<=1 newest group pending)
        asm volatile("cp.async.wait_group 1;" ::: "memory");
        __syncthreads();

        load_stage(t + 2);

        const uint32_t bufb = sb + (uint32_t)(t % NSTAGE) * SM_BUFSZ;

#pragma unroll
        for (int ks = 0; ks < 4; ++ks) {
            const int kc = ks * 2;  // 16B-chunk index of this k16 step

            // A fragments (rows = M): 4 x m16 (64-row warp slab)
            uint32_t fA[4][4];
#pragma unroll
            for (int mb = 0; mb < 4; ++mb) {
                const int row = warp_m * 64 + mb * 16 + lj + ((lsel & 1) << 3);
                const int ch  = kc + (lsel >> 1);
                ldm_x4(fA[mb], bufb +
                       SMEM_SWIZZLE_128B((uint32_t)(row * 128 + ch * 16)));
            }

            // B fragments (rows = N): 4 x n16 (64-col warp slab)
            uint32_t fB[4][4];
#pragma unroll
            for (int nb = 0; nb < 4; ++nb) {
                const int row = warp_n * 64 + nb * 16 + lj + ((lsel >> 1) << 3);
                const int ch  = kc + (lsel & 1);
                ldm_x4(fB[nb], bufb + 16384 +
                       SMEM_SWIZZLE_128B((uint32_t)(row * 128 + ch * 16)));
            }

            // 32 HMMA per ks
#pragma unroll
            for (int mb = 0; mb < 4; ++mb) {
#pragma unroll
                for (int nb = 0; nb < 4; ++nb) {
                    mma_fp16(d[mb][nb * 2 + 0], fA[mb], fB[nb][0], fB[nb][1]);
                    mma_fp16(d[mb][nb * 2 + 1], fA[mb], fB[nb][2], fB[nb][3]);
                }
            }
        }
    }

    asm volatile("cp.async.wait_group 0;" ::: "memory");

    // ---- epilogue: regs -> gmem via f32 reduction (bias pre-filled) -------
    // d-frag: d0,d1 -> row (lid>>2),   cols (lid&3)*2 + {0,1}
    //         d2,d3 -> row (lid>>2)+8, same cols
    const int rw = rbase + warp_m * 64 + (lid >> 2);
    const int cw = nbase + warp_n * 64 + (lid & 3) * 2;
#pragma unroll
    for (int mb = 0; mb < 4; ++mb) {
#pragma unroll
        for (int q = 0; q < 8; ++q) {
            const int col = cw + q * 8;
            const int r0  = rw + mb * 16;
            red_add_v2(out + (size_t)r0 * N_DIM + col,
                       d[mb][q][0], d[mb][q][1]);
            red_add_v2(out + (size_t)(r0 + 8) * N_DIM + col,
                       d[mb][q][2], d[mb][q][3]);
        }
    }
}

// ---------------- launch ----------------------------------------------------
extern "C" void kernel_launch(void* const* d_in, const int* in_sizes, int n_in,
                              void* d_out, int out_size)
{
    const float* x    = (const float*)d_in[0];
    const float* a[8] = {(const float*)d_in[1], (const float*)d_in[2],
                         (const float*)d_in[3], (const float*)d_in[4],
                         (const float*)d_in[5], (const float*)d_in[6],
                         (const float*)d_in[7], (const float*)d_in[8]};
    const float* b[8] = {(const float*)d_in[9],  (const float*)d_in[10],
                         (const float*)d_in[11], (const float*)d_in[12],
                         (const float*)d_in[13], (const float*)d_in[14],
                         (const float*)d_in[15], (const float*)d_in[16]};
    const float* bias = (const float*)d_in[17];
    float* out = (float*)d_out;

    cudaFuncSetAttribute(gemm_kernel,
                         cudaFuncAttributeMaxDynamicSharedMemorySize,
                         SMEM_TOTAL);

    // 1) fused prep: W build (blocks 0..8191) + X convert/out init (rest)
    prep_kernel<<<24576, 256>>>(
        x, bias, out,
        a[0], a[1], a[2], a[3], a[4], a[5], a[6], a[7],
        b[0], b[1], b[2], b[3], b[4], b[5], b[6], b[7]);

    // 2) GEMM: 32x32x2 grid (128x128 tiles, K split in 2), 128 threads
    gemm_kernel<<<dim3(32, 32, 2), 128, SMEM_TOTAL>>>(out);
}

// round 17
// speedup vs baseline: 1.2924x; 1.0168x over previous
#include <cuda_runtime.h>
#include <cuda_bf16.h>
#include <cuda_fp16.h>
#include <cstdint>

// ============================================================================
// KLinear: y[i,n] = (sum_k kron(a_k,b_k)[i,j] / (2*sqrt(8))) * x[n,j] + bias[n]
//
// fp16 single-product GEMM (calibrated rel_err 2.93e-4), fp32 accum.
// Round-17: GEMM = R14/R16 verbatim (local optimum: 308us, tensor 73.2%;
// 3-CTA/SM, 64x32-warp, and two-stage-Kron variants all ruled out by RF /
// smem-crossbar / traffic accounting). Prep kernel now INTERLEAVES W-build
// (L1-bound) and X-convert/out-init (DRAM-bound) blocks by blockIdx%3 so
// the two phases co-execute on disjoint pipes instead of serializing.
// ============================================================================

#define N_DIM 4096

// ---------------- scratch (device globals; no runtime allocation) ----------
__device__ __half g_Wh[(size_t)N_DIM * N_DIM];
__device__ __half g_Xh[(size_t)N_DIM * N_DIM];

// ---------------- helpers ---------------------------------------------------
#define SMEM_SWIZZLE_128B(o) ((o) ^ (((o) >> 3) & 0x70))

__device__ __forceinline__ uint32_t smem_u32(const void* p) {
    uint32_t a;
    asm("{ .reg .u64 t; cvta.to.shared.u64 t, %1; cvt.u32.u64 %0, t; }"
        : "=r"(a) : "l"(p));
    return a;
}

__device__ __forceinline__ void cp_async16(uint32_t dst, const void* src) {
    asm volatile("cp.async.cg.shared.global [%0], [%1], 16;"
                 :: "r"(dst), "l"(src) : "memory");
}

__device__ __forceinline__ void ldm_x4(uint32_t (&r)[4], uint32_t addr) {
    asm volatile("ldmatrix.sync.aligned.m8n8.x4.shared.b16 {%0,%1,%2,%3}, [%4];"
                 : "=r"(r[0]), "=r"(r[1]), "=r"(r[2]), "=r"(r[3])
                 : "r"(addr));
}

__device__ __forceinline__ void mma_fp16(float (&d)[4], const uint32_t (&a)[4],
                                         uint32_t b0, uint32_t b1) {
    asm volatile(
        "mma.sync.aligned.m16n8k16.row.col.f32.f16.f16.f32 "
        "{%0,%1,%2,%3}, {%4,%5,%6,%7}, {%8,%9}, {%0,%1,%2,%3};"
        : "+f"(d[0]), "+f"(d[1]), "+f"(d[2]), "+f"(d[3])
        : "r"(a[0]), "r"(a[1]), "r"(a[2]), "r"(a[3]), "r"(b0), "r"(b1));
}

__device__ __forceinline__ void red_add_v2(float* ptr, float v0, float v1) {
    asm volatile("red.global.add.v2.f32 [%0], {%1, %2};"
                 :: "l"(ptr), "f"(v0), "f"(v1) : "memory");
}

// ---------------- kernel 1: fused prep (interleaved phases) ----------------
// blockIdx % 3 == 0 (8192 blocks):  build W (fp32 math) -> fp16, 8/thread
// blockIdx % 3 != 0 (16384 blocks): X -> fp16  AND  out := broadcast(bias)
__global__ __launch_bounds__(256) void prep_kernel(
    const float* __restrict__ x, const float* __restrict__ bias,
    float* __restrict__ out,
    const float* __restrict__ a0, const float* __restrict__ a1,
    const float* __restrict__ a2, const float* __restrict__ a3,
    const float* __restrict__ a4, const float* __restrict__ a5,
    const float* __restrict__ a6, const float* __restrict__ a7,
    const float* __restrict__ b0, const float* __restrict__ b1,
    const float* __restrict__ b2, const float* __restrict__ b3,
    const float* __restrict__ b4, const float* __restrict__ b5,
    const float* __restrict__ b6, const float* __restrict__ b7)
{
    const int bidx = blockIdx.x;
    const int rem  = bidx % 3;
    if (rem == 0) {
        // ---- W build: 2.097M threads x 8 outputs ----
        const int t = (bidx / 3) * 256 + threadIdx.x;
        const int i  = t >> 9;          // row 0..4095
        const int j0 = (t & 511) << 3;  // 8-aligned col

        const float av0 = a0[(i >> 6) * 64  + (j0 >> 6)];
        const float av1 = a1[(i >> 6) * 64  + (j0 >> 6)];
        const float av2 = a2[(i >> 7) * 32  + (j0 >> 7)];
        const float av3 = a3[(i >> 5) * 128 + (j0 >> 5)];
        const float av4 = a4[(i >> 8) * 16  + (j0 >> 8)];
        const float av5 = a5[(i >> 4) * 256 + (j0 >> 4)];
        const float av6 = a6[(i >> 9) * 8   + (j0 >> 9)];
        const float av7 = a7[(i >> 3) * 512 + (j0 >> 3)];

        const float4* p0 = reinterpret_cast<const float4*>(b0 + (i & 63)  * 64  + (j0 & 63));
        const float4* p1 = reinterpret_cast<const float4*>(b1 + (i & 63)  * 64  + (j0 & 63));
        const float4* p2 = reinterpret_cast<const float4*>(b2 + (i & 127) * 128 + (j0 & 127));
        const float4* p3 = reinterpret_cast<const float4*>(b3 + (i & 31)  * 32  + (j0 & 31));
        const float4* p4 = reinterpret_cast<const float4*>(b4 + (i & 255) * 256 + (j0 & 255));
        const float4* p5 = reinterpret_cast<const float4*>(b5 + (i & 15)  * 16  + (j0 & 15));
        const float4* p6 = reinterpret_cast<const float4*>(b6 + (i & 511) * 512 + (j0 & 511));
        const float4* p7 = reinterpret_cast<const float4*>(b7 + (i & 7)   * 8   + (j0 & 7));

        float s[8];
#pragma unroll
        for (int e = 0; e < 8; ++e) s[e] = 0.0f;

#pragma unroll
        for (int h = 0; h < 2; ++h) {
            float4 v0 = p0[h], v1 = p1[h], v2 = p2[h], v3 = p3[h];
            float4 v4 = p4[h], v5 = p5[h], v6 = p6[h], v7 = p7[h];
            float* e0 = &v0.x; float* e1 = &v1.x; float* e2 = &v2.x; float* e3 = &v3.x;
            float* e4 = &v4.x; float* e5 = &v5.x; float* e6 = &v6.x; float* e7 = &v7.x;
#pragma unroll
            for (int e = 0; e < 4; ++e) {
                float acc = av0 * e0[e];
                acc = fmaf(av1, e1[e], acc);
                acc = fmaf(av2, e2[e], acc);
                acc = fmaf(av3, e3[e], acc);
                acc = fmaf(av4, e4[e], acc);
                acc = fmaf(av5, e5[e], acc);
                acc = fmaf(av6, e6[e], acc);
                acc = fmaf(av7, e7[e], acc);
                s[h * 4 + e] = acc * 0.17677669529663687f;  // 1/(2*sqrt(8))
            }
        }

        __half h8[8];
#pragma unroll
        for (int e = 0; e < 8; ++e) h8[e] = __float2half_rn(s[e]);
        *reinterpret_cast<uint4*>(g_Wh + (size_t)i * N_DIM + j0) =
            *reinterpret_cast<uint4*>(h8);
    } else {
        // ---- X convert + out init: 4.19M float4 threads ----
        const int xb = (bidx / 3) * 2 + (rem - 1);
        const int i  = xb * 256 + threadIdx.x;
        float4 v = reinterpret_cast<const float4*>(x)[i];
        __half2 h0 = __floats2half2_rn(v.x, v.y);
        __half2 h1 = __floats2half2_rn(v.z, v.w);
        reinterpret_cast<__half2*>(g_Xh)[2 * i]     = h0;
        reinterpret_cast<__half2*>(g_Xh)[2 * i + 1] = h1;

        reinterpret_cast<float4*>(out)[i] =
            reinterpret_cast<const float4*>(bias)[i & 1023];
    }
}

// ---------------- kernel 2: fp16 mma.sync GEMM (R14 verbatim) ---------------
// CTA tile 128(M) x 128(N), K-half = 2048 (32 ktiles of 64), 128 threads
// (4 warps, 2Mx2N, warp tile 64x64). SMEM: 3 stages x 32KB:
//   +0      W (128 x 64 fp16, SW128-swizzled 128B rows)  = 16KB
//   +16384  X (128 x 64 fp16)                            = 16KB
static constexpr int SM_BUFSZ   = 32768;
static constexpr int NSTAGE     = 3;
static constexpr int SMEM_TOTAL = NSTAGE * SM_BUFSZ;  // 98304
static constexpr int KTILES     = 32;                 // per K-half

__global__ __launch_bounds__(128, 2)
void gemm_kernel(float* __restrict__ out)
{
    extern __shared__ __align__(1024) char smem[];
    const uint32_t sb = smem_u32(smem);
    const int tid = threadIdx.x;
    const int wid = tid >> 5;
    const int lid = tid & 31;

    const int rbase = blockIdx.x * 128;        // M rows (W / OUTF)
    const int nbase = blockIdx.y * 128;        // N rows (X / BATCH)
    const int kbase = blockIdx.z * 2048;       // K half

    const int warp_m = wid & 1;   // 0..1 -> 64-row slab
    const int warp_n = wid >> 1;  // 0..1 -> 64-col slab

    const int lj   = lid & 7;   // row-within-8 for ldmatrix
    const int lsel = lid >> 3;  // which 8x8 matrix this lane feeds

    // ---- cp.async stage loader: 2048 chunks of 16B, 16 per thread ---------
    auto load_stage = [&](int t) {
        if (t < KTILES) {
            const uint32_t bufb =
                sb + (uint32_t)(t % NSTAGE) * SM_BUFSZ;
            const int k0 = kbase + t * 64;
#pragma unroll
            for (int s = 0; s < 8; ++s) {        // W: 1024 chunks (128 rows)
                const int c   = tid + s * 128;
                const int row = c >> 3;
                const int ch  = c & 7;
                const uint32_t sw =
                    SMEM_SWIZZLE_128B((uint32_t)(row * 128 + ch * 16));
                cp_async16(bufb + sw,
                           g_Wh + (size_t)(rbase + row) * N_DIM + k0 + ch * 8);
            }
#pragma unroll
            for (int s = 0; s < 8; ++s) {        // X: 1024 chunks (128 rows)
                const int c   = tid + s * 128;
                const int row = c >> 3;
                const int ch  = c & 7;
                const uint32_t sw =
                    SMEM_SWIZZLE_128B((uint32_t)(row * 128 + ch * 16));
                cp_async16(bufb + 16384 + sw,
                           g_Xh + (size_t)(nbase + row) * N_DIM + k0 + ch * 8);
            }
        }
        asm volatile("cp.async.commit_group;" ::: "memory");
    };

    // ---- accumulators: 4 m16-blocks x 8 n8-blocks x 4 regs = 128 ----------
    float d[4][8][4];
#pragma unroll
    for (int mb = 0; mb < 4; ++mb)
#pragma unroll
        for (int q = 0; q < 8; ++q)
#pragma unroll
            for (int r = 0; r < 4; ++r) d[mb][q][r] = 0.0f;

    load_stage(0);
    load_stage(1);

    for (int t = 0; t < KTILES; ++t) {
        // stage t resident (<=1 newest group pending)
        asm volatile("cp.async.wait_group 1;" ::: "memory");
        __syncthreads();

        load_stage(t + 2);

        const uint32_t bufb = sb + (uint32_t)(t % NSTAGE) * SM_BUFSZ;

#pragma unroll
        for (int ks = 0; ks < 4; ++ks) {
            const int kc = ks * 2;  // 16B-chunk index of this k16 step

            // A fragments (rows = M): 4 x m16 (64-row warp slab)
            uint32_t fA[4][4];
#pragma unroll
            for (int mb = 0; mb < 4; ++mb) {
                const int row = warp_m * 64 + mb * 16 + lj + ((lsel & 1) << 3);
                const int ch  = kc + (lsel >> 1);
                ldm_x4(fA[mb], bufb +
                       SMEM_SWIZZLE_128B((uint32_t)(row * 128 + ch * 16)));
            }

            // B fragments (rows = N): 4 x n16 (64-col warp slab)
            uint32_t fB[4][4];
#pragma unroll
            for (int nb = 0; nb < 4; ++nb) {
                const int row = warp_n * 64 + nb * 16 + lj + ((lsel >> 1) << 3);
                const int ch  = kc + (lsel & 1);
                ldm_x4(fB[nb], bufb + 16384 +
                       SMEM_SWIZZLE_128B((uint32_t)(row * 128 + ch * 16)));
            }

            // 32 HMMA per ks
#pragma unroll
            for (int mb = 0; mb < 4; ++mb) {
#pragma unroll
                for (int nb = 0; nb < 4; ++nb) {
                    mma_fp16(d[mb][nb * 2 + 0], fA[mb], fB[nb][0], fB[nb][1]);
                    mma_fp16(d[mb][nb * 2 + 1], fA[mb], fB[nb][2], fB[nb][3]);
                }
            }
        }
    }

    asm volatile("cp.async.wait_group 0;" ::: "memory");

    // ---- epilogue: regs -> gmem via f32 reduction (bias pre-filled) -------
    // d-frag: d0,d1 -> row (lid>>2),   cols (lid&3)*2 + {0,1}
    //         d2,d3 -> row (lid>>2)+8, same cols
    const int rw = rbase + warp_m * 64 + (lid >> 2);
    const int cw = nbase + warp_n * 64 + (lid & 3) * 2;
#pragma unroll
    for (int mb = 0; mb < 4; ++mb) {
#pragma unroll
        for (int q = 0; q < 8; ++q) {
            const int col = cw + q * 8;
            const int r0  = rw + mb * 16;
            red_add_v2(out + (size_t)r0 * N_DIM + col,
                       d[mb][q][0], d[mb][q][1]);
            red_add_v2(out + (size_t)(r0 + 8) * N_DIM + col,
                       d[mb][q][2], d[mb][q][3]);
        }
    }
}

// ---------------- launch ----------------------------------------------------
extern "C" void kernel_launch(void* const* d_in, const int* in_sizes, int n_in,
                              void* d_out, int out_size)
{
    const float* x    = (const float*)d_in[0];
    const float* a[8] = {(const float*)d_in[1], (const float*)d_in[2],
                         (const float*)d_in[3], (const float*)d_in[4],
                         (const float*)d_in[5], (const float*)d_in[6],
                         (const float*)d_in[7], (const float*)d_in[8]};
    const float* b[8] = {(const float*)d_in[9],  (const float*)d_in[10],
                         (const float*)d_in[11], (const float*)d_in[12],
                         (const float*)d_in[13], (const float*)d_in[14],
                         (const float*)d_in[15], (const float*)d_in[16]};
    const float* bias = (const float*)d_in[17];
    float* out = (float*)d_out;

    cudaFuncSetAttribute(gemm_kernel,
                         cudaFuncAttributeMaxDynamicSharedMemorySize,
                         SMEM_TOTAL);

    // 1) fused prep, phases interleaved by blockIdx%3:
    //    rem==0 -> W build (8192 blocks); rem!=0 -> X convert/out init (16384)
    prep_kernel<<<24576, 256>>>(
        x, bias, out,
        a[0], a[1], a[2], a[3], a[4], a[5], a[6], a[7],
        b[0], b[1], b[2], b[3], b[4], b[5], b[6], b[7]);

    // 2) GEMM: 32x32x2 grid (128x128 tiles, K split in 2), 128 threads
    gemm_kernel<<<dim3(32, 32, 2), 128, SMEM_TOTAL>>>(out);
}